// round 14
// baseline (speedup 1.0000x reference)
#include <cuda_runtime.h>
#include <cuda_fp16.h>
#include <cstdint>
#include <cstring>

#define BB 4
#define CC 256
#define HH 180
#define WW 320
#define DD 64
#define HW (HH * WW)

#define XT 128           // M tile (x per CTA)
#define NXT 3            // ceil(320/128)
#define NTILES (NXT * HH * BB)  // 2160
#define KC 16            // channels per chunk
#define NCHUNK (CC / KC) // 16
#define NTHREADS 256     // 8 warps, warp w -> rows 16w..16w+15
#define GRIDX 456        // 152 SMs x 3 CTAs, persistent

// smem (bytes). k-major, 16B-padded rows for conflict-free ldmatrix
#define SA_STRIDE 272            // 128 halfs + pad = 17 * 16B
#define SB_STRIDE 400            // 192 halfs + pad = 25 * 16B
#define SA_BYTES (KC * SA_STRIDE)        // 4352
#define SB_BYTES (KC * SB_STRIDE)        // 6400
#define SB_BASE (2 * SA_BYTES)           // 8704
#define SOUT_STRIDE 132                  // floats
#define SMEM_BYTES (DD * SOUT_STRIDE * 4)  // 33792 >= 2*(SA+SB) = 21504

static __device__ __forceinline__ uint32_t smem_u32(const void* p) {
    uint32_t a;
    asm("{ .reg .u64 t; cvta.to.shared.u64 t, %1; cvt.u32.u64 %0, t; }"
        : "=r"(a) : "l"(p));
    return a;
}

static __device__ __forceinline__ void ldsm4t(uint32_t& r0, uint32_t& r1,
                                              uint32_t& r2, uint32_t& r3,
                                              uint32_t addr) {
    asm volatile("ldmatrix.sync.aligned.m8n8.x4.trans.shared.b16 {%0,%1,%2,%3}, [%4];"
                 : "=r"(r0), "=r"(r1), "=r"(r2), "=r"(r3) : "r"(addr));
}

static __device__ __forceinline__ void mma16816(float* c,
                                                uint32_t a0, uint32_t a1,
                                                uint32_t a2, uint32_t a3,
                                                uint32_t b0, uint32_t b1) {
    asm volatile("mma.sync.aligned.m16n8k16.row.col.f32.f16.f16.f32 "
                 "{%0,%1,%2,%3},{%4,%5,%6,%7},{%8,%9},{%0,%1,%2,%3};"
                 : "+f"(c[0]), "+f"(c[1]), "+f"(c[2]), "+f"(c[3])
                 : "r"(a0), "r"(a1), "r"(a2), "r"(a3), "r"(b0), "r"(b1));
}

static __device__ __forceinline__ uint32_t pack_h2(float x, float y) {
    __half2 h = __floats2half2_rn(x, y);
    uint32_t u;
    memcpy(&u, &h, 4);
    return u;
}

__global__ __launch_bounds__(NTHREADS, 3)
void cost_volume_hmma(const float* __restrict__ Lp,
                      const float* __restrict__ Rp,
                      float* __restrict__ out) {
    __shared__ __align__(16) char sBuf[SMEM_BYTES];

    const int tid = threadIdx.x;
    const int wid = tid >> 5;
    const int lid = tid & 31;

    const uint32_t sbase = smem_u32(sBuf);

    // ---- tile-invariant per-thread loader constants ----
    // A: 16 c-rows x 32 quads (128 x) = 512 quads, 2/thread
    const int a_xq4 = (tid & 31) * 4;
    int a_cHW[2];
#pragma unroll
    for (int p = 0; p < 2; ++p) a_cHW[p] = ((tid >> 5) + 8 * p) * HW;
    // B: 16 c-rows x 48 quads (192 y) = 768 quads, 3/thread
    const int b_cHW = (tid >> 4) * HW;
    int b_yq4[3];
#pragma unroll
    for (int p = 0; p < 3; ++p) b_yq4[p] = ((tid & 15) + p * 16) * 4;

    // smem store offsets (tile-invariant)
    int a_soff[2], b_soff[3];
#pragma unroll
    for (int p = 0; p < 2; ++p)
        a_soff[p] = ((tid >> 5) + 8 * p) * SA_STRIDE + (tid & 31) * 8;
#pragma unroll
    for (int p = 0; p < 3; ++p)
        b_soff[p] = (tid >> 4) * SB_STRIDE + ((tid & 15) + p * 16) * 8;

    // ---- ldmatrix per-lane offsets ----
    const uint32_t a_loff =
        (uint32_t)(((lid & 7) + ((lid >> 4) & 1) * 8) * SA_STRIDE +
                   (16 * wid + ((lid >> 3) & 1) * 8) * 2);
    const uint32_t b_loff =
        (uint32_t)(((lid & 7) + ((lid >> 3) & 1) * 8) * SB_STRIDE +
                   (16 * wid + ((lid >> 4) & 1) * 8) * 2);

    float acc[10][4];
    float4 aq[2], bq[3];         // dist-1 staging: 20 registers
    const float4 zero4 = make_float4(0.f, 0.f, 0.f, 0.f);

    // ---- persistent tile loop ----
#pragma unroll 1
    for (int tile = blockIdx.x; tile < NTILES; tile += GRIDX) {
        const int xtile = tile % NXT;
        const int hh = (tile / NXT) % HH;
        const int bb = tile / (NXT * HH);
        const int x0 = xtile * XT;
        const float* Lrow = Lp + (size_t)bb * CC * HW + (size_t)hh * WW;
        const float* Rrow = Rp + (size_t)bb * CC * HW + (size_t)hh * WW;

        const int a_gx = x0 + a_xq4;
        const bool aok = a_gx < WW;
        int b_gy[3];
        bool bok[3];
#pragma unroll
        for (int p = 0; p < 3; ++p) {
            b_gy[p] = x0 - 64 + b_yq4[p];
            bok[p] = (b_gy[p] >= 0) && (b_gy[p] < WW);
        }

        auto ldg_chunk = [&](int k) {
            const float* Lc = Lrow + (size_t)k * KC * HW;
            const float* Rc = Rrow + (size_t)k * KC * HW;
#pragma unroll
            for (int p = 0; p < 2; ++p)
                aq[p] = aok ? __ldcs((const float4*)(Lc + a_cHW[p] + a_gx))
                            : zero4;
#pragma unroll
            for (int p = 0; p < 3; ++p)
                bq[p] = bok[p] ? *(const float4*)(Rc + b_cHW + b_gy[p]) : zero4;
        };

        auto sts_chunk = [&](int buf) {
#pragma unroll
            for (int p = 0; p < 2; ++p) {
                uint2 u;
                u.x = pack_h2(aq[p].x, aq[p].y);
                u.y = pack_h2(aq[p].z, aq[p].w);
                *(uint2*)(sBuf + buf * SA_BYTES + a_soff[p]) = u;
            }
#pragma unroll
            for (int p = 0; p < 3; ++p) {
                uint2 u;
                u.x = pack_h2(bq[p].x, bq[p].y);
                u.y = pack_h2(bq[p].z, bq[p].w);
                *(uint2*)(sBuf + SB_BASE + buf * SB_BYTES + b_soff[p]) = u;
            }
        };

        auto compute = [&](int buf) {
            const uint32_t abase = sbase + (uint32_t)(buf * SA_BYTES) + a_loff;
            const uint32_t bbase =
                sbase + (uint32_t)(SB_BASE + buf * SB_BYTES) + b_loff;
            uint32_t a0, a1, a2, a3;
            ldsm4t(a0, a1, a2, a3, abase);
#pragma unroll
            for (int tp = 0; tp < 5; ++tp) {
                uint32_t b0, b1, b2, b3;
                ldsm4t(b0, b1, b2, b3, bbase + (uint32_t)(tp * 32));
                mma16816(acc[2 * tp],     a0, a1, a2, a3, b0, b1);
                mma16816(acc[2 * tp + 1], a0, a1, a2, a3, b2, b3);
            }
        };

#pragma unroll
        for (int t = 0; t < 10; ++t)
#pragma unroll
            for (int j = 0; j < 4; ++j) acc[t][j] = 0.0f;

        // prologue: chunk 0
        ldg_chunk(0);
        sts_chunk(0);
        __syncthreads();

        // mainloop: ldg(k+1) / compute(k) / sts(k+1)
#pragma unroll 1
        for (int k = 0; k < NCHUNK; ++k) {
            const bool pre = (k + 1 < NCHUNK);
            if (pre) ldg_chunk(k + 1);
            compute(k & 1);
            if (pre) sts_chunk((k + 1) & 1);
            __syncthreads();
        }

        // ---- epilogue: diagonal remap into sOut[i][x], i = x - y ----
        float* sOut = (float*)sBuf;
        const float sc = 1.0f / 256.0f;
        const int g = lid >> 2;
        const int tg = lid & 3;
#pragma unroll
        for (int t = 0; t < 10; ++t) {
#pragma unroll
            for (int j = 0; j < 4; ++j) {
                const int r = g + (j >> 1) * 8;
                const int cn = 2 * tg + (j & 1);
                const int i = r + 64 - 8 * t - cn;   // disparity
                if (i >= 0 && i < DD)
                    sOut[i * SOUT_STRIDE + 16 * wid + r] = acc[t][j] * sc;
            }
        }
        __syncthreads();

        // ---- coalesced float4 streaming stores ----
        {
            const int xl4 = lid * 4;
            if (x0 + xl4 < WW) {
#pragma unroll
                for (int i = wid; i < DD; i += 8) {
                    float4 v = *(const float4*)&sOut[i * SOUT_STRIDE + xl4];
                    __stcs((float4*)&out[(((size_t)bb * DD + i) * HH + hh) * WW +
                                         x0 + xl4], v);
                }
            }
        }
        __syncthreads();   // sOut reads done before next tile's sts overwrites
    }
}

extern "C" void kernel_launch(void* const* d_in, const int* in_sizes, int n_in,
                              void* d_out, int out_size) {
    const float* left  = (const float*)d_in[0];
    const float* right = (const float*)d_in[1];
    float* out = (float*)d_out;
    (void)in_sizes; (void)n_in; (void)out_size;

    dim3 grid(GRIDX);          // persistent: 152 SMs x 3 CTAs
    dim3 block(NTHREADS);
    cost_volume_hmma<<<grid, block>>>(left, right, out);
}